// round 15
// baseline (speedup 1.0000x reference)
#include <cuda_runtime.h>
#include <math.h>

#define B_G 32
#define N_G 256
#define D_G 128
#define T_G 8192

// ---------------- device scratch (no allocation) ----------------
__device__ float g_tmp[T_G * D_G];
__device__ float g_keys[T_G * D_G];
__device__ float g_gi[T_G * 3 * D_G];

// ---------------- fast math ----------------
__device__ __forceinline__ float fexp2(float x) {
    float y; asm("ex2.approx.f32 %0, %1;" : "=f"(y) : "f"(x)); return y;
}
__device__ __forceinline__ float fexpf_(float x) { return fexp2(x * 1.4426950408889634f); }
__device__ __forceinline__ float ftanh(float x) {
    float e = fexp2(x * 2.8853900817779268f);
    return 1.0f - __fdividef(2.0f, e + 1.0f);
}

// ---------------- precompute GEMMs (R10-proven) ----------------
__device__ __forceinline__ void gemm_tile(
    const float* __restrict__ A, const float* __restrict__ W,
    const float* __restrict__ bias, float* __restrict__ C,
    int N, int relu, int m0, int n0, int tid)
{
    __shared__ float As[64 * 129];
    __shared__ float Ws[64 * 129];

    for (int i = tid; i < 64 * 32; i += 256) {
        int r = i >> 5, kq = i & 31;
        float4 a = *((const float4*)(A + (size_t)(m0 + r) * 128) + kq);
        float* p = As + r * 129 + kq * 4;
        p[0] = a.x; p[1] = a.y; p[2] = a.z; p[3] = a.w;
        float4 w = *((const float4*)(W + (size_t)(n0 + r) * 128) + kq);
        float* pw = Ws + r * 129 + kq * 4;
        pw[0] = w.x; pw[1] = w.y; pw[2] = w.z; pw[3] = w.w;
    }
    __syncthreads();

    const int tx = tid & 15, ty = tid >> 4;
    float acc[4][4] = {};
    const float* ap = As + ty * 4 * 129;
    const float* wp = Ws + tx * 4 * 129;
#pragma unroll 4
    for (int k = 0; k < 128; k++) {
        float a0 = ap[k], a1 = ap[129 + k], a2 = ap[258 + k], a3 = ap[387 + k];
        float w0 = wp[k], w1 = wp[129 + k], w2 = wp[258 + k], w3 = wp[387 + k];
        acc[0][0] += a0 * w0; acc[0][1] += a0 * w1; acc[0][2] += a0 * w2; acc[0][3] += a0 * w3;
        acc[1][0] += a1 * w0; acc[1][1] += a1 * w1; acc[1][2] += a1 * w2; acc[1][3] += a1 * w3;
        acc[2][0] += a2 * w0; acc[2][1] += a2 * w1; acc[2][2] += a2 * w2; acc[2][3] += a2 * w3;
        acc[3][0] += a3 * w0; acc[3][1] += a3 * w1; acc[3][2] += a3 * w2; acc[3][3] += a3 * w3;
    }

    float4 b4;
    b4.x = bias[n0 + tx * 4 + 0]; b4.y = bias[n0 + tx * 4 + 1];
    b4.z = bias[n0 + tx * 4 + 2]; b4.w = bias[n0 + tx * 4 + 3];
#pragma unroll
    for (int i = 0; i < 4; i++) {
        float4 o;
        o.x = acc[i][0] + b4.x; o.y = acc[i][1] + b4.y;
        o.z = acc[i][2] + b4.z; o.w = acc[i][3] + b4.w;
        if (relu) {
            o.x = fmaxf(o.x, 0.f); o.y = fmaxf(o.y, 0.f);
            o.z = fmaxf(o.z, 0.f); o.w = fmaxf(o.w, 0.f);
        }
        *(float4*)(C + (size_t)(m0 + ty * 4 + i) * N + n0 + tx * 4) = o;
    }
}

__global__ __launch_bounds__(256) void gemm_fused(
    const float* __restrict__ emb,
    const float* __restrict__ Wk1, const float* __restrict__ bk1,
    const float* __restrict__ Wih, const float* __restrict__ bih)
{
    int bx = blockIdx.x;
    if (bx < 256)
        gemm_tile(emb, Wk1, bk1, g_tmp, 128, 1, (bx >> 1) * 64, (bx & 1) * 64, threadIdx.x);
    else {
        int j = bx - 256;
        gemm_tile(emb, Wih, bih, g_gi, 384, 0, (j / 6) * 64, (j % 6) * 64, threadIdx.x);
    }
}

__global__ __launch_bounds__(256) void gemm_tn(
    const float* __restrict__ A, const float* __restrict__ W,
    const float* __restrict__ bias, float* __restrict__ C, int N, int relu)
{
    gemm_tile(A, W, bias, C, N, relu, blockIdx.x * 64, blockIdx.y * 64, threadIdx.x);
}

__global__ void l2norm_rows(float* __restrict__ X, int rows)
{
    int wid = threadIdx.x >> 5, lane = threadIdx.x & 31;
    int row = blockIdx.x * 8 + wid;
    if (row >= rows) return;
    float4* p = (float4*)(X + (size_t)row * 128) + lane;
    float4 x = *p;
    float ss = x.x * x.x + x.y * x.y + x.z * x.z + x.w * x.w;
#pragma unroll
    for (int o = 16; o; o >>= 1) ss += __shfl_xor_sync(0xffffffffu, ss, o);
    float rn = 1.0f / fmaxf(sqrtf(ss), 1e-12f);
    x.x *= rn; x.y *= rn; x.z *= rn; x.w *= rn;
    *p = x;
}

// ---------------- single-CTA 512-thread decoder (no cluster) --------------
// dyn smem: KEYS full graph, [n*128 + d], 256*128 floats = 131072 B
#define DYN_FLOATS 32768

__global__ __launch_bounds__(512, 1)
void decode_kernel(
    const float* __restrict__ emb, const int* __restrict__ start_nodes,
    const float* __restrict__ W_hh, const float* __restrict__ b_hh,
    const float* __restrict__ Wq1, const float* __restrict__ bq1,
    const float* __restrict__ Wq2, const float* __restrict__ bq2,
    const float* __restrict__ Wh,  const float* __restrict__ bh,
    const float* __restrict__ v,
    float* __restrict__ out_f, int* __restrict__ out_i, int mode)
{
    extern __shared__ float KEYS[];   // [n*128 + d]

    __shared__ __align__(16) float hbuf[2][128];
    __shared__ __align__(16) float q_s[128], hq_s[128], gctx_s[128];
    __shared__ float ghbuf[384];
    __shared__ float red_s[16];
    __shared__ float wm1[10], wm2[10], we_s[10];
    __shared__ int   wn1[10], wn2[10];
    __shared__ int   list_s[256], pos_s[256];
    __shared__ int   cnt_s, cur_s, cnd1_s, cnd2_s;
    __shared__ float fm1_s, fm2_s, acc1_s, acc2_s, M_s, E_s;

    const int tid  = threadIdx.x;
    const int lane = tid & 31, wid = tid >> 5;   // 16 warps
    const int b    = blockIdx.x;
    const int base = b * N_G;

    // register-resident Wq1/Wq2: 4 threads per output, 32 floats each
    const int ro = tid >> 2, rq = tid & 3;
    float4 w1r[8], w2r[8];
    float bq1r, bq2r;
    {
        const float4* p1 = (const float4*)(Wq1 + (size_t)ro * 128 + rq * 32);
        const float4* p2 = (const float4*)(Wq2 + (size_t)ro * 128 + rq * 32);
#pragma unroll
        for (int j = 0; j < 8; j++) { w1r[j] = p1[j]; w2r[j] = p2[j]; }
        bq1r = bq1[ro]; bq2r = bq2[ro];
    }
    // gh duty (warps 10-15): thread gt handles rows gt and gt+192
    const int gt = tid - 320;
    float bhh0 = 0.f, bhh1 = 0.f;
    if (gt >= 0) { bhh0 = b_hh[gt]; bhh1 = b_hh[gt + 192]; }

    // ---- staging: all 256 keys -> smem ----
    for (int idx = tid; idx < 256 * 32; idx += 512) {
        int n = idx >> 5, kq = idx & 31;
        ((float4*)(KEYS + n * 128))[kq] =
            __ldg((const float4*)(g_keys + (size_t)(base + n) * 128) + kq);
    }
    if (tid < 256) { list_s[tid] = tid; pos_s[tid] = tid; }
    if (tid == 0) { cnt_s = 256; cur_s = start_nodes[b] - base; }
    if (tid < 128) {
        float acc = 0.f;
        const float* ep = emb + (size_t)base * 128 + tid;
#pragma unroll 8
        for (int n = 0; n < 256; n++) acc += ep[n * 128];
        gctx_s[tid] = acc * (1.0f / 256.0f);
    }
    __syncthreads();
    // h0 = Wh @ gctx + bh (16 warps x 8 rows)
    {
        float4 g4 = *((const float4*)gctx_s + lane);
#pragma unroll
        for (int i = 0; i < 8; i++) {
            int r = wid * 8 + i;
            float4 w4 = *((const float4*)(Wh + (size_t)r * 128) + lane);
            float s = w4.x * g4.x + w4.y * g4.y + w4.z * g4.z + w4.w * g4.w;
#pragma unroll
            for (int o = 16; o; o >>= 1) s += __shfl_xor_sync(0xffffffffu, s, o);
            if (lane == 0) hbuf[0][r] = s + bh[r];
        }
    }
    float4 v4 = *((const float4*)v + lane);
    __syncthreads();
    // gh(0): 384 threads x 1 row, W_hh streamed from gmem
    if (tid < 384) {
        const float4* wp = (const float4*)(W_hh + (size_t)tid * 128);
        const float4* hb = (const float4*)hbuf[0];
        float a0 = 0.f, a1 = 0.f, a2 = 0.f, a3 = 0.f;
#pragma unroll 8
        for (int k = 0; k < 32; k++) {
            float4 w = __ldg(wp + k);
            float4 h4 = hb[k];
            a0 += w.x * h4.x; a1 += w.y * h4.y;
            a2 += w.z * h4.z; a3 += w.w * h4.w;
        }
        ghbuf[tid] = (a0 + a1) + (a2 + a3) + b_hh[tid];
    }
    __syncthreads();

    for (int step = 0; step < N_G - 1; step++) {
        const int buf = step & 1, nbuf = buf ^ 1;
        const int curg = cur_s;

        // (d) GRU full (threads 0-127, accurate gates); tid==128 removes node
        if (tid < 128) {
            const float* gip = g_gi + (size_t)(base + curg) * 384 + tid;
            float gi_r = __ldg(gip);
            float gi_z = __ldg(gip + 128);
            float gi_n = __ldg(gip + 256);
            float gr_ = 1.f / (1.f + expf(-(gi_r + ghbuf[tid])));
            float gz  = 1.f / (1.f + expf(-(gi_z + ghbuf[128 + tid])));
            float gn  = tanhf(gi_n + gr_ * ghbuf[256 + tid]);
            hbuf[nbuf][tid] = (1.f - gz) * gn + gz * hbuf[buf][tid];
        } else if (tid == 128) {
            int p = pos_s[curg], last = cnt_s - 1;
            int tail = list_s[last];
            list_s[p] = tail; pos_s[tail] = p;
            cnt_s = last;
        }
        __syncthreads();

        // (e) stage1: 512 threads, 4 per output, Wq1 in regs
        {
            const float4* h4p = (const float4*)(hbuf[nbuf] + rq * 32);
            float p0 = 0.f, p1 = 0.f, p2 = 0.f, p3 = 0.f;
#pragma unroll
            for (int j = 0; j < 8; j += 4) {
                float4 h0 = h4p[j], h1 = h4p[j+1], h2 = h4p[j+2], h3 = h4p[j+3];
                p0 += w1r[j].x * h0.x + w1r[j].y * h0.y + w1r[j].z * h0.z + w1r[j].w * h0.w;
                p1 += w1r[j+1].x * h1.x + w1r[j+1].y * h1.y + w1r[j+1].z * h1.z + w1r[j+1].w * h1.w;
                p2 += w1r[j+2].x * h2.x + w1r[j+2].y * h2.y + w1r[j+2].z * h2.z + w1r[j+2].w * h2.w;
                p3 += w1r[j+3].x * h3.x + w1r[j+3].y * h3.y + w1r[j+3].z * h3.z + w1r[j+3].w * h3.w;
            }
            float p = (p0 + p1) + (p2 + p3);
            p += __shfl_xor_sync(0xffffffffu, p, 1);
            p += __shfl_xor_sync(0xffffffffu, p, 2);
            if (rq == 0) hq_s[ro] = fmaxf(p + bq1r, 0.f);
        }
        __syncthreads();

        // (f) stage2 + q sum-of-squares
        {
            const float4* h4p = (const float4*)(hq_s + rq * 32);
            float p0 = 0.f, p1 = 0.f, p2 = 0.f, p3 = 0.f;
#pragma unroll
            for (int j = 0; j < 8; j += 4) {
                float4 h0 = h4p[j], h1 = h4p[j+1], h2 = h4p[j+2], h3 = h4p[j+3];
                p0 += w2r[j].x * h0.x + w2r[j].y * h0.y + w2r[j].z * h0.z + w2r[j].w * h0.w;
                p1 += w2r[j+1].x * h1.x + w2r[j+1].y * h1.y + w2r[j+1].z * h1.z + w2r[j+1].w * h1.w;
                p2 += w2r[j+2].x * h2.x + w2r[j+2].y * h2.y + w2r[j+2].z * h2.z + w2r[j+2].w * h2.w;
                p3 += w2r[j+3].x * h3.x + w2r[j+3].y * h3.y + w2r[j+3].z * h3.z + w2r[j+3].w * h3.w;
            }
            float p = (p0 + p1) + (p2 + p3);
            p += __shfl_xor_sync(0xffffffffu, p, 1);
            p += __shfl_xor_sync(0xffffffffu, p, 2);
            float qv = 0.f;
            if (rq == 0) { qv = p + bq2r; q_s[ro] = qv; }
            float q2 = qv * qv;
#pragma unroll
            for (int o = 16; o; o >>= 1) q2 += __shfl_xor_sync(0xffffffffu, q2, o);
            if (lane == 0) red_s[wid] = q2;
        }
        __syncthreads();

        const int cnt = cnt_s;
        float ssum = 0.f;
#pragma unroll
        for (int w = 0; w < 16; w++) ssum += red_s[w];
        const float rn = rsqrtf(fmaxf(ssum, 1e-24f));
        float4 q4 = *((const float4*)q_s + lane);
        q4.x *= rn; q4.y *= rn; q4.z *= rn; q4.w *= rn;

        // (g) scoring (warps 0-9, smem keys, 2-node ILP)
        //     || gh(t+1) from gmem W_hh (warps 10-15, 2 rows/thread)
        if (wid < 10) {
            float m1 = -INFINITY, m2 = -INFINITY, em = -INFINITY, esum = 0.f;
            int n1 = 0x7fffffff, n2 = 0x7fffffff;
            for (int p = wid; p < cnt; p += 20) {
                int nlA = list_s[p];
                int pB = p + 10;
                bool hasB = pB < cnt;
                int nlB = hasB ? list_s[pB] : nlA;
                float4 kA = *((const float4*)(KEYS + nlA * 128) + lane);
                float4 kB = *((const float4*)(KEYS + nlB * 128) + lane);
                float sA = v4.x * ftanh(kA.x + q4.x) + v4.y * ftanh(kA.y + q4.y)
                         + v4.z * ftanh(kA.z + q4.z) + v4.w * ftanh(kA.w + q4.w);
                float sB = v4.x * ftanh(kB.x + q4.x) + v4.y * ftanh(kB.y + q4.y)
                         + v4.z * ftanh(kB.z + q4.z) + v4.w * ftanh(kB.w + q4.w);
#pragma unroll
                for (int o = 16; o; o >>= 1) {
                    sA += __shfl_xor_sync(0xffffffffu, sA, o);
                    sB += __shfl_xor_sync(0xffffffffu, sB, o);
                }
                if (lane == 0) {
                    if (sA > m1 || (sA == m1 && nlA < n1)) { m2 = m1; n2 = n1; m1 = sA; n1 = nlA; }
                    else if (sA > m2 || (sA == m2 && nlA < n2)) { m2 = sA; n2 = nlA; }
                    float sB2 = hasB ? sB : -INFINITY;
                    if (hasB) {
                        if (sB > m1 || (sB == m1 && nlB < n1)) { m2 = m1; n2 = n1; m1 = sB; n1 = nlB; }
                        else if (sB > m2 || (sB == m2 && nlB < n2)) { m2 = sB; n2 = nlB; }
                    }
                    float mn = fmaxf(em, fmaxf(sA, sB2));
                    esum = esum * fexpf_(em - mn) + fexpf_(sA - mn) + fexpf_(sB2 - mn);
                    em = mn;
                }
            }
            if (lane == 0) {
                wm1[wid] = m1; wn1[wid] = n1; wm2[wid] = m2; wn2[wid] = n2;
                we_s[wid] = esum;
            }
        } else {
            const float4* wp0 = (const float4*)(W_hh + (size_t)gt * 128);
            const float4* wp1 = (const float4*)(W_hh + (size_t)(gt + 192) * 128);
            const float4* hb = (const float4*)hbuf[nbuf];
            float a0 = 0.f, a1 = 0.f, b0 = 0.f, b1 = 0.f;
#pragma unroll 8
            for (int k = 0; k < 32; k++) {
                float4 h4 = hb[k];
                float4 w0 = __ldg(wp0 + k);
                float4 w1 = __ldg(wp1 + k);
                a0 += w0.x * h4.x + w0.y * h4.y;
                a1 += w0.z * h4.z + w0.w * h4.w;
                b0 += w1.x * h4.x + w1.y * h4.y;
                b1 += w1.z * h4.z + w1.w * h4.w;
            }
            ghbuf[gt]       = a0 + a1 + bhh0;
            ghbuf[gt + 192] = b0 + b1 + bhh1;
        }
        __syncthreads();

        // (h') warps 0,1: top2 merge (redundant) + accurate rescore of cnd1/cnd2;
        //      warp 2: (M,E) merge
        if (wid < 2) {
            float bm1 = -INFINITY, bm2 = -INFINITY;
            int bn1 = 0x7fffffff, bn2 = 0x7fffffff;
#pragma unroll
            for (int w = 0; w < 10; w++) {
#pragma unroll
                for (int c = 0; c < 2; c++) {
                    float s = c ? wm2[w] : wm1[w];
                    int   n = c ? wn2[w] : wn1[w];
                    if (s > bm1 || (s == bm1 && n < bn1)) { bm2 = bm1; bn2 = bn1; bm1 = s; bn1 = n; }
                    else if (s > bm2 || (s == bm2 && n < bn2)) { bm2 = s; bn2 = n; }
                }
            }
            int mycnd = wid ? bn2 : bn1;
            float acc = -INFINITY;
            if (mycnd != 0x7fffffff) {
                float4 k4 = *((const float4*)(KEYS + mycnd * 128) + lane);
                float s = v4.x * tanhf(k4.x + q4.x) + v4.y * tanhf(k4.y + q4.y)
                        + v4.z * tanhf(k4.z + q4.z) + v4.w * tanhf(k4.w + q4.w);
#pragma unroll
                for (int o = 16; o; o >>= 1) s += __shfl_xor_sync(0xffffffffu, s, o);
                acc = s;
            }
            if (lane == 0) {
                if (wid == 0) {
                    cnd1_s = bn1; cnd2_s = bn2;
                    fm1_s = bm1; fm2_s = bm2;
                    acc1_s = acc;
                } else {
                    acc2_s = acc;
                }
            }
        } else if (wid == 2) {
            float mw = (lane < 10) ? wm1[lane] : -INFINITY;
            float ew = (lane < 10) ? we_s[lane] : 0.f;
            float M = mw;
#pragma unroll
            for (int o = 16; o; o >>= 1) M = fmaxf(M, __shfl_xor_sync(0xffffffffu, M, o));
            float term = (ew > 0.f) ? ew * fexpf_(mw - M) : 0.f;  // NaN guard
#pragma unroll
            for (int o = 16; o; o >>= 1) term += __shfl_xor_sync(0xffffffffu, term, o);
            if (lane == 0) { M_s = M; E_s = term; }
        }
        __syncthreads();

        // (k) tid0: pick winner (accurate scores, lowest-id tie-break), logp, output
        if (tid == 0) {
            float a1 = acc1_s, a2 = acc2_s;
            int c1 = cnd1_s, c2 = cnd2_s;
            int win; float fwin;
            if (a2 > a1 || (a2 == a1 && c2 < c1)) { win = c2; fwin = fm2_s; }
            else                                   { win = c1; fwin = fm1_s; }
            float prob = __fdividef(fexpf_(fwin - M_s), E_s);
            float lp = logf(prob + 1e-10f);
            cur_s = win;
            if (mode == 0) {
                out_f[b * N_G + step] = (float)(base + curg);
                out_f[B_G * N_G + b * (N_G - 1) + step] = lp;
            } else if (mode == 1) {
                out_i[b * N_G + step] = base + curg;
            } else {
                out_f[b * (N_G - 1) + step] = lp;
            }
        }
        __syncthreads();
    }

    if (tid == 0) {
        if (mode == 0)      out_f[b * N_G + (N_G - 1)] = (float)(base + cur_s);
        else if (mode == 1) out_i[b * N_G + (N_G - 1)] = base + cur_s;
    }
}

// ---------------- launch ----------------
extern "C" void kernel_launch(void* const* d_in, const int* in_sizes, int n_in,
                              void* d_out, int out_size) {
    const float* emb   = (const float*)d_in[0];
    const int*   start = (const int*)d_in[1];
    const float* Wq1 = (const float*)d_in[3];
    const float* bq1 = (const float*)d_in[4];
    const float* Wq2 = (const float*)d_in[5];
    const float* bq2 = (const float*)d_in[6];
    const float* Wk1 = (const float*)d_in[7];
    const float* bk1 = (const float*)d_in[8];
    const float* Wk2 = (const float*)d_in[9];
    const float* bk2 = (const float*)d_in[10];
    const float* W_ih = (const float*)d_in[11];
    const float* W_hh = (const float*)d_in[12];
    const float* b_ih = (const float*)d_in[13];
    const float* b_hh = (const float*)d_in[14];
    const float* v    = (const float*)d_in[15];
    const float* Wh   = (const float*)d_in[16];
    const float* bh   = (const float*)d_in[17];
    (void)in_sizes; (void)n_in;

    void *p_tmp, *p_keys;
    cudaGetSymbolAddress(&p_tmp, g_tmp);
    cudaGetSymbolAddress(&p_keys, g_keys);
    float* tmp  = (float*)p_tmp;
    float* keys = (float*)p_keys;

    gemm_fused<<<1024, 256>>>(emb, Wk1, bk1, W_ih, b_ih);
    gemm_tn<<<dim3(T_G / 64, D_G / 64), 256>>>(tmp, Wk2, bk2, keys, D_G, 0);
    l2norm_rows<<<T_G / 8, 256>>>(keys, T_G);

    int mode = 0;
    if (out_size == B_G * N_G + B_G * (N_G - 1)) mode = 0;
    else if (out_size == B_G * N_G) mode = 1;
    else if (out_size == B_G * (N_G - 1)) mode = 2;

    static int smem_set = -1;
    size_t dyn = DYN_FLOATS * sizeof(float);
    if (smem_set < 0) {
        cudaFuncSetAttribute(decode_kernel,
                             cudaFuncAttributeMaxDynamicSharedMemorySize, (int)dyn);
        smem_set = 1;
    }
    decode_kernel<<<B_G, 512, dyn>>>(emb, start, W_hh, b_hh,
                                     Wq1, bq1, Wq2, bq2, Wh, bh, v,
                                     (float*)d_out, (int*)d_out, mode);
}

// round 16
// speedup vs baseline: 2.2536x; 2.2536x over previous
#include <cuda_runtime.h>
#include <math.h>

#define B_G 32
#define N_G 256
#define D_G 128
#define T_G 8192

// ---------------- device scratch (no allocation) ----------------
__device__ float g_tmp[T_G * D_G];
__device__ float g_keys[T_G * D_G];
__device__ float g_gi[T_G * 3 * D_G];

// ---------------- fast math ----------------
__device__ __forceinline__ float fexp2(float x) {
    float y; asm("ex2.approx.f32 %0, %1;" : "=f"(y) : "f"(x)); return y;
}
__device__ __forceinline__ float fexpf_(float x) { return fexp2(x * 1.4426950408889634f); }
__device__ __forceinline__ float ftanh(float x) {
    float e = fexp2(x * 2.8853900817779268f);
    return 1.0f - __fdividef(2.0f, e + 1.0f);
}

// ---------------- cluster/mbarrier helpers ----------------
__device__ __forceinline__ unsigned mapa_sh(unsigned a, unsigned r) {
    unsigned o; asm("mapa.shared::cluster.u32 %0, %1, %2;" : "=r"(o) : "r"(a), "r"(r));
    return o;
}
__device__ __forceinline__ unsigned ctarank() {
    unsigned r; asm("mov.u32 %0, %%cluster_ctarank;" : "=r"(r)); return r;
}
__device__ __forceinline__ void st_remote_f32(unsigned addr, float v) {
    asm volatile("st.shared::cluster.f32 [%0], %1;" :: "r"(addr), "f"(v) : "memory");
}
__device__ __forceinline__ void prefetch_l1(const float* p) {
    asm volatile("prefetch.global.L1 [%0];" :: "l"(p));
}
#define MBAR_INIT(a, c) \
    asm volatile("mbarrier.init.shared.b64 [%0], %1;" :: "r"(a), "r"(c) : "memory")
#define MBAR_ARRIVE_LOCAL(a) \
    asm volatile("mbarrier.arrive.shared.b64 _, [%0];" :: "r"(a) : "memory")
#define MBAR_ARRIVE_REMOTE(a, rk) \
    asm volatile("{\n\t.reg .b32 ra;\n\tmapa.shared::cluster.u32 ra, %0, %1;\n\t" \
                 "mbarrier.arrive.shared::cluster.b64 _, [ra];\n\t}" \
                 :: "r"(a), "r"(rk) : "memory")
#define MBAR_WAIT(mbar, par) do {                                             \
    unsigned _m = (mbar), _p = (par), _d;                                     \
    asm volatile("{\n\t.reg .pred p;\n\t"                                     \
        "mbarrier.try_wait.parity.acquire.cta.shared::cta.b64 p, [%1], %2;\n\t" \
        "selp.b32 %0, 1, 0, p;\n\t}"                                          \
        : "=r"(_d) : "r"(_m), "r"(_p) : "memory");                            \
    if (!_d) {                                                                \
        asm volatile("{\n\t.reg .pred P1;\n\tWL%=:\n\t"                       \
            "mbarrier.try_wait.parity.acquire.cta.shared::cta.b64 P1, [%0], %1, 0x989680;\n\t" \
            "@P1 bra WD%=;\n\tbra WL%=;\n\tWD%=:\n\t}"                        \
            :: "r"(_m), "r"(_p) : "memory");                                  \
    }                                                                         \
} while (0)
#define FENCE_CLUSTER() asm volatile("fence.acq_rel.cluster;" ::: "memory")
#define CLUSTER_SYNC_() do {                                        \
    asm volatile("barrier.cluster.arrive.aligned;" ::: "memory");   \
    asm volatile("barrier.cluster.wait.aligned;"   ::: "memory");   \
} while (0)

// ---------------- precompute GEMMs (R10-proven) ----------------
__device__ __forceinline__ void gemm_tile(
    const float* __restrict__ A, const float* __restrict__ W,
    const float* __restrict__ bias, float* __restrict__ C,
    int N, int relu, int m0, int n0, int tid)
{
    __shared__ float As[64 * 129];
    __shared__ float Ws[64 * 129];

    for (int i = tid; i < 64 * 32; i += 256) {
        int r = i >> 5, kq = i & 31;
        float4 a = *((const float4*)(A + (size_t)(m0 + r) * 128) + kq);
        float* p = As + r * 129 + kq * 4;
        p[0] = a.x; p[1] = a.y; p[2] = a.z; p[3] = a.w;
        float4 w = *((const float4*)(W + (size_t)(n0 + r) * 128) + kq);
        float* pw = Ws + r * 129 + kq * 4;
        pw[0] = w.x; pw[1] = w.y; pw[2] = w.z; pw[3] = w.w;
    }
    __syncthreads();

    const int tx = tid & 15, ty = tid >> 4;
    float acc[4][4] = {};
    const float* ap = As + ty * 4 * 129;
    const float* wp = Ws + tx * 4 * 129;
#pragma unroll 4
    for (int k = 0; k < 128; k++) {
        float a0 = ap[k], a1 = ap[129 + k], a2 = ap[258 + k], a3 = ap[387 + k];
        float w0 = wp[k], w1 = wp[129 + k], w2 = wp[258 + k], w3 = wp[387 + k];
        acc[0][0] += a0 * w0; acc[0][1] += a0 * w1; acc[0][2] += a0 * w2; acc[0][3] += a0 * w3;
        acc[1][0] += a1 * w0; acc[1][1] += a1 * w1; acc[1][2] += a1 * w2; acc[1][3] += a1 * w3;
        acc[2][0] += a2 * w0; acc[2][1] += a2 * w1; acc[2][2] += a2 * w2; acc[2][3] += a2 * w3;
        acc[3][0] += a3 * w0; acc[3][1] += a3 * w1; acc[3][2] += a3 * w2; acc[3][3] += a3 * w3;
    }

    float4 b4;
    b4.x = bias[n0 + tx * 4 + 0]; b4.y = bias[n0 + tx * 4 + 1];
    b4.z = bias[n0 + tx * 4 + 2]; b4.w = bias[n0 + tx * 4 + 3];
#pragma unroll
    for (int i = 0; i < 4; i++) {
        float4 o;
        o.x = acc[i][0] + b4.x; o.y = acc[i][1] + b4.y;
        o.z = acc[i][2] + b4.z; o.w = acc[i][3] + b4.w;
        if (relu) {
            o.x = fmaxf(o.x, 0.f); o.y = fmaxf(o.y, 0.f);
            o.z = fmaxf(o.z, 0.f); o.w = fmaxf(o.w, 0.f);
        }
        *(float4*)(C + (size_t)(m0 + ty * 4 + i) * N + n0 + tx * 4) = o;
    }
}

__global__ __launch_bounds__(256) void gemm_fused(
    const float* __restrict__ emb,
    const float* __restrict__ Wk1, const float* __restrict__ bk1,
    const float* __restrict__ Wih, const float* __restrict__ bih)
{
    int bx = blockIdx.x;
    if (bx < 256)
        gemm_tile(emb, Wk1, bk1, g_tmp, 128, 1, (bx >> 1) * 64, (bx & 1) * 64, threadIdx.x);
    else {
        int j = bx - 256;
        gemm_tile(emb, Wih, bih, g_gi, 384, 0, (j / 6) * 64, (j % 6) * 64, threadIdx.x);
    }
}

__global__ __launch_bounds__(256) void gemm_tn(
    const float* __restrict__ A, const float* __restrict__ W,
    const float* __restrict__ bias, float* __restrict__ C, int N, int relu)
{
    gemm_tile(A, W, bias, C, N, relu, blockIdx.x * 64, blockIdx.y * 64, threadIdx.x);
}

__global__ void l2norm_rows(float* __restrict__ X, int rows)
{
    int wid = threadIdx.x >> 5, lane = threadIdx.x & 31;
    int row = blockIdx.x * 8 + wid;
    if (row >= rows) return;
    float4* p = (float4*)(X + (size_t)row * 128) + lane;
    float4 x = *p;
    float ss = x.x * x.x + x.y * x.y + x.z * x.z + x.w * x.w;
#pragma unroll
    for (int o = 16; o; o >>= 1) ss += __shfl_xor_sync(0xffffffffu, ss, o);
    float rn = 1.0f / fmaxf(sqrtf(ss), 1e-12f);
    x.x *= rn; x.y *= rn; x.z *= rn; x.w *= rn;
    *p = x;
}

// ---------------- clustered decoder: redundant GRU via shadowed gh partials
// dyn smem (floats):
//   WCOL  [k*385 + j]  k<32, j<384 : 12320   (W_hh column slice, padded)
//   KEYS  [n*128 + d]  n<64        :  8192   @ 12320
//   GHPART[pb][r][384] 2*4*384     :  3072   @ 20512
#define WCOL_OFF 0
#define KEY_OFF  12320
#define GHP_OFF  20512
#define DYN_FLOATS 23584

__global__ __launch_bounds__(256, 1) __cluster_dims__(4, 1, 1)
void decode_kernel(
    const float* __restrict__ emb, const int* __restrict__ start_nodes,
    const float* __restrict__ W_hh, const float* __restrict__ b_hh,
    const float* __restrict__ Wq1, const float* __restrict__ bq1,
    const float* __restrict__ Wq2, const float* __restrict__ bq2,
    const float* __restrict__ Wh,  const float* __restrict__ bh,
    const float* __restrict__ v,
    float* __restrict__ out_f, int* __restrict__ out_i, int mode)
{
    extern __shared__ float dyn[];
    float* WCOL   = dyn + WCOL_OFF;
    float* KEYS   = dyn + KEY_OFF;
    float* GHPART = dyn + GHP_OFF;   // [(pb*4 + r)*384 + j]

    __shared__ __align__(16) float hbuf[2][128];
    __shared__ __align__(16) float q_s[128], hq_s[128], gctx_s[128];
    __shared__ float stats_s[2][4][8];
    __shared__ float bhh_s[384], bq1_s[128], bq2_s[128];
    __shared__ float wm1[8], wm2[8], we_s[8], red_s[8];
    __shared__ int   wn1[8], wn2[8];
    __shared__ int   list_s[64], pos_s[64];
    __shared__ int   cnt_s, cur_s, cnd1_s, cnd2_s;
    __shared__ __align__(8) unsigned long long stat_mbar, gh_mbar;

    const int tid  = threadIdx.x;
    const int lane = tid & 31, wid = tid >> 5;
    const unsigned rank = ctarank();
    const int b    = blockIdx.x >> 2;
    const int base = b * N_G;

    // register-resident Wq1/Wq2: 2 threads per output, 64 floats each
    const int ro = tid >> 1, rkh = tid & 1;
    float4 w1r[16], w2r[16];
    {
        const float4* p1 = (const float4*)(Wq1 + (size_t)ro * 128 + rkh * 64);
        const float4* p2 = (const float4*)(Wq2 + (size_t)ro * 128 + rkh * 64);
#pragma unroll
        for (int j = 0; j < 16; j++) { w1r[j] = p1[j]; w2r[j] = p2[j]; }
    }

    // ---- staging ----
    // W_hh column slice: WCOL[k*385 + j] = W_hh[j*128 + rank*32 + k]
    for (int idx = tid; idx < 384 * 32; idx += 256) {
        int j = idx >> 5, k = idx & 31;               // coalesced read over k
        WCOL[k * 385 + j] = W_hh[(size_t)j * 128 + rank * 32 + k];
    }
    for (int idx = tid; idx < 64 * 32; idx += 256) {  // own 64 keys
        int n = idx >> 5, kq = idx & 31;
        ((float4*)(KEYS + n * 128))[kq] =
            *((const float4*)(g_keys + (size_t)(base + (int)rank * 64 + n) * 128) + kq);
    }
    for (int i = tid; i < 384; i += 256) bhh_s[i] = b_hh[i];
    if (tid < 128) { bq1_s[tid] = bq1[tid]; bq2_s[tid] = bq2[tid]; }
    if (tid < 64) { list_s[tid] = tid; pos_s[tid] = tid; }
    if (tid == 0) {
        cnt_s = 64; cur_s = start_nodes[b] - base;
        MBAR_INIT((unsigned)__cvta_generic_to_shared(&stat_mbar), 4);
        MBAR_INIT((unsigned)__cvta_generic_to_shared(&gh_mbar), 12);
    }
    // graph context (redundant per CTA)
    if (tid < 128) {
        float acc = 0.f;
        const float* ep = emb + (size_t)base * 128 + tid;
#pragma unroll 8
        for (int n = 0; n < 256; n++) acc += ep[n * 128];
        gctx_s[tid] = acc * (1.0f / 256.0f);
    }
    __syncthreads();
    // h0 = Wh @ gctx + bh
    {
        float4 g4 = *((const float4*)gctx_s + lane);
#pragma unroll
        for (int i = 0; i < 16; i++) {
            int r = wid * 16 + i;
            float4 w4 = *((const float4*)(Wh + (size_t)r * 128) + lane);
            float s = w4.x * g4.x + w4.y * g4.y + w4.z * g4.z + w4.w * g4.w;
#pragma unroll
            for (int o = 16; o; o >>= 1) s += __shfl_xor_sync(0xffffffffu, s, o);
            if (lane == 0) hbuf[0][r] = s + bh[r];
        }
    }
    float4 v4 = *((const float4*)v + lane);
    __syncthreads();
    CLUSTER_SYNC_();   // all mbars initialized before any remote traffic

    const unsigned smb = (unsigned)__cvta_generic_to_shared(&stat_mbar);
    const unsigned gmb = (unsigned)__cvta_generic_to_shared(&gh_mbar);

    // ---- prologue: gh(0) partials from h0, push, arrive (phase 0) ----
    if (wid >= 1 && wid <= 3) {
        int pt = tid - 32;   // 0..95 ; rows pt, pt+96, pt+192, pt+288
        const float* hown = hbuf[0] + rank * 32;
        float r0 = 0.f, r1 = 0.f, r2 = 0.f, r3 = 0.f;
#pragma unroll 8
        for (int k = 0; k < 32; k++) {
            float hk = hown[k];
            const float* w = WCOL + k * 385 + pt;
            r0 += w[0]   * hk; r1 += w[96]  * hk;
            r2 += w[192] * hk; r3 += w[288] * hk;
        }
        float* dst = GHPART + (0 * 4 + rank) * 384 + pt;
        dst[0] = r0; dst[96] = r1; dst[192] = r2; dst[288] = r3;
        unsigned da = (unsigned)__cvta_generic_to_shared(dst);
#pragma unroll
        for (unsigned pr = 0; pr < 4; pr++)
            if (pr != rank) {
                unsigned ra = mapa_sh(da, pr);
                st_remote_f32(ra, r0);
                st_remote_f32(ra + 96 * 4, r1);
                st_remote_f32(ra + 192 * 4, r2);
                st_remote_f32(ra + 288 * 4, r3);
            }
        __syncwarp();
        if (lane == 0) {
            FENCE_CLUSTER();
            MBAR_ARRIVE_LOCAL(gmb);
#pragma unroll
            for (unsigned pr = 0; pr < 4; pr++)
                if (pr != rank) MBAR_ARRIVE_REMOTE(gmb, pr);
        }
    }

    for (int step = 0; step < N_G - 1; step++) {
        const int buf = step & 1, nbuf = buf ^ 1, sbuf = step & 1;
        const int curg = cur_s;

        // (d) GRU full + redundant (threads 0-127); fixed-order partial sum
        if (tid < 128) {
            MBAR_WAIT(gmb, step & 1);
            FENCE_CLUSTER();
            const float* P = GHPART + (size_t)(step & 1) * 4 * 384;
            float gh_r = ((P[tid]        + P[384 + tid])
                        + (P[768 + tid]  + P[1152 + tid])) + bhh_s[tid];
            float gh_z = ((P[128 + tid]  + P[512 + tid])
                        + (P[896 + tid]  + P[1280 + tid])) + bhh_s[128 + tid];
            float gh_n = ((P[256 + tid]  + P[640 + tid])
                        + (P[1024 + tid] + P[1408 + tid])) + bhh_s[256 + tid];
            const float* gip = g_gi + (size_t)(base + curg) * 384 + tid;
            float gi_r = __ldg(gip);
            float gi_z = __ldg(gip + 128);
            float gi_n = __ldg(gip + 256);
            float gr_ = 1.f / (1.f + expf(-(gi_r + gh_r)));
            float gz  = 1.f / (1.f + expf(-(gi_z + gh_z)));
            float gn  = tanhf(gi_n + gr_ * gh_n);
            hbuf[nbuf][tid] = (1.f - gz) * gn + gz * hbuf[buf][tid];
        } else if (tid == 128) {
            if ((curg >> 6) == (int)rank) {
                int nl = curg & 63;
                int p = pos_s[nl], last = cnt_s - 1;
                int tail = list_s[last];
                list_s[p] = tail; pos_s[tail] = p;
                cnt_s = last;
            }
        }
        __syncthreads();

        // (e) stage1: all 256 threads, Wq1 in registers
        {
            const float4* h4p = (const float4*)(hbuf[nbuf] + rkh * 64);
            float p0 = 0.f, p1 = 0.f, p2 = 0.f, p3 = 0.f;
#pragma unroll
            for (int j = 0; j < 16; j += 4) {
                float4 h0 = h4p[j], h1 = h4p[j + 1], h2 = h4p[j + 2], h3 = h4p[j + 3];
                p0 += w1r[j].x * h0.x + w1r[j].y * h0.y + w1r[j].z * h0.z + w1r[j].w * h0.w;
                p1 += w1r[j+1].x * h1.x + w1r[j+1].y * h1.y + w1r[j+1].z * h1.z + w1r[j+1].w * h1.w;
                p2 += w1r[j+2].x * h2.x + w1r[j+2].y * h2.y + w1r[j+2].z * h2.z + w1r[j+2].w * h2.w;
                p3 += w1r[j+3].x * h3.x + w1r[j+3].y * h3.y + w1r[j+3].z * h3.z + w1r[j+3].w * h3.w;
            }
            float p = (p0 + p1) + (p2 + p3);
            p += __shfl_xor_sync(0xffffffffu, p, 1);
            if (rkh == 0) hq_s[ro] = fmaxf(p + bq1_s[ro], 0.f);
        }
        __syncthreads();

        // (f) stage2 + q sum-of-squares partials
        {
            const float4* h4p = (const float4*)(hq_s + rkh * 64);
            float p0 = 0.f, p1 = 0.f, p2 = 0.f, p3 = 0.f;
#pragma unroll
            for (int j = 0; j < 16; j += 4) {
                float4 h0 = h4p[j], h1 = h4p[j + 1], h2 = h4p[j + 2], h3 = h4p[j + 3];
                p0 += w2r[j].x * h0.x + w2r[j].y * h0.y + w2r[j].z * h0.z + w2r[j].w * h0.w;
                p1 += w2r[j+1].x * h1.x + w2r[j+1].y * h1.y + w2r[j+1].z * h1.z + w2r[j+1].w * h1.w;
                p2 += w2r[j+2].x * h2.x + w2r[j+2].y * h2.y + w2r[j+2].z * h2.z + w2r[j+2].w * h2.w;
                p3 += w2r[j+3].x * h3.x + w2r[j+3].y * h3.y + w2r[j+3].z * h3.z + w2r[j+3].w * h3.w;
            }
            float p = (p0 + p1) + (p2 + p3);
            p += __shfl_xor_sync(0xffffffffu, p, 1);
            float qv = 0.f;
            if (rkh == 0) { qv = p + bq2_s[ro]; q_s[ro] = qv; }
            float q2 = qv * qv;
#pragma unroll
            for (int o = 16; o; o >>= 1) q2 += __shfl_xor_sync(0xffffffffu, q2, o);
            if (lane == 0) red_s[wid] = q2;
        }
        __syncthreads();

        // common q4
        const int cnt = cnt_s;
        const float rn = rsqrtf(fmaxf(red_s[0] + red_s[1] + red_s[2] + red_s[3]
                                    + red_s[4] + red_s[5] + red_s[6] + red_s[7], 1e-24f));
        float4 q4 = *((const float4*)q_s + lane);
        q4.x *= rn; q4.y *= rn; q4.z *= rn; q4.w *= rn;

        // (g) scoring: ALL 8 warps, smem keys, 2-node ILP (R10-identical)
        {
            float m1 = -INFINITY, m2 = -INFINITY, em = -INFINITY, esum = 0.f;
            int n1 = 0x7fffffff, n2 = 0x7fffffff;
            for (int p = wid; p < cnt; p += 16) {
                int nlA = list_s[p];
                int pB = p + 8;
                bool hasB = pB < cnt;
                int nlB = hasB ? list_s[pB] : nlA;
                float4 kA = *((const float4*)(KEYS + nlA * 128) + lane);
                float4 kB = *((const float4*)(KEYS + nlB * 128) + lane);
                float sA = v4.x * ftanh(kA.x + q4.x) + v4.y * ftanh(kA.y + q4.y)
                         + v4.z * ftanh(kA.z + q4.z) + v4.w * ftanh(kA.w + q4.w);
                float sB = v4.x * ftanh(kB.x + q4.x) + v4.y * ftanh(kB.y + q4.y)
                         + v4.z * ftanh(kB.z + q4.z) + v4.w * ftanh(kB.w + q4.w);
#pragma unroll
                for (int o = 16; o; o >>= 1) {
                    sA += __shfl_xor_sync(0xffffffffu, sA, o);
                    sB += __shfl_xor_sync(0xffffffffu, sB, o);
                }
                if (lane == 0) {
                    int ngA = (int)rank * 64 + nlA;
                    if (sA > m1 || (sA == m1 && ngA < n1)) { m2 = m1; n2 = n1; m1 = sA; n1 = ngA; }
                    else if (sA > m2 || (sA == m2 && ngA < n2)) { m2 = sA; n2 = ngA; }
                    float sB2 = hasB ? sB : -INFINITY;
                    if (hasB) {
                        int ngB = (int)rank * 64 + nlB;
                        if (sB > m1 || (sB == m1 && ngB < n1)) { m2 = m1; n2 = n1; m1 = sB; n1 = ngB; }
                        else if (sB > m2 || (sB == m2 && ngB < n2)) { m2 = sB; n2 = ngB; }
                    }
                    float mn = fmaxf(em, fmaxf(sA, sB2));
                    esum = esum * fexpf_(em - mn) + fexpf_(sA - mn) + fexpf_(sB2 - mn);
                    em = mn;
                }
            }
            if (lane == 0) {
                wm1[wid] = m1; wn1[wid] = n1; wm2[wid] = m2; wn2[wid] = n2;
                we_s[wid] = esum;
            }
        }
        __syncthreads();

        // (h') warps 0,1: top2 merge + accurate rescore; warp 2: (M,E) merge
        float* row = stats_s[sbuf][rank];
        if (wid < 2) {
            float bm1 = -INFINITY, bm2 = -INFINITY;
            int bn1 = 0x7fffffff, bn2 = 0x7fffffff;
#pragma unroll
            for (int w = 0; w < 8; w++) {
#pragma unroll
                for (int c = 0; c < 2; c++) {
                    float s = c ? wm2[w] : wm1[w];
                    int   n = c ? wn2[w] : wn1[w];
                    if (s > bm1 || (s == bm1 && n < bn1)) { bm2 = bm1; bn2 = bn1; bm1 = s; bn1 = n; }
                    else if (s > bm2 || (s == bm2 && n < bn2)) { bm2 = s; bn2 = n; }
                }
            }
            int mycnd = wid ? bn2 : bn1;
            float acc = -INFINITY;
            if (mycnd != 0x7fffffff) {
                int nl = mycnd & 63;
                float4 k4 = *((const float4*)(KEYS + nl * 128) + lane);
                float s = v4.x * tanhf(k4.x + q4.x) + v4.y * tanhf(k4.y + q4.y)
                        + v4.z * tanhf(k4.z + q4.z) + v4.w * tanhf(k4.w + q4.w);
#pragma unroll
                for (int o = 16; o; o >>= 1) s += __shfl_xor_sync(0xffffffffu, s, o);
                acc = s;
            }
            if (lane == 0) {
                if (wid == 0) {
                    row[0] = acc;
                    row[1] = bm1; row[2] = __int_as_float(bn1);
                    row[4] = bm2; row[5] = __int_as_float(bn2);
                    cnd1_s = bn1; cnd2_s = bn2;
                } else {
                    row[3] = acc;
                }
            }
        } else if (wid == 2) {
            float mw = (lane < 8) ? wm1[lane] : -INFINITY;
            float ew = (lane < 8) ? we_s[lane] : 0.f;
            float M = mw;
#pragma unroll
            for (int o = 16; o; o >>= 1) M = fmaxf(M, __shfl_xor_sync(0xffffffffu, M, o));
            float term = (ew > 0.f) ? ew * fexpf_(mw - M) : 0.f;  // NaN guard
#pragma unroll
            for (int o = 16; o; o >>= 1) term += __shfl_xor_sync(0xffffffffu, term, o);
            if (lane == 0) { row[6] = M; row[7] = term; }
        }
        __syncthreads();

        // (j) warp0: push stats row + arrive;
        //     warps 1-3: gh(t+1) PARTIALS from h(t) + push + arrive (shadowed);
        //     warps 4,5: L1-prefetch candidate gi rows
        if (wid == 0) {
            if (lane < 8) {
                float val = row[lane];
                unsigned ra = (unsigned)__cvta_generic_to_shared(&row[lane]);
#pragma unroll
                for (unsigned pr = 0; pr < 4; pr++)
                    if (pr != rank) st_remote_f32(mapa_sh(ra, pr), val);
            }
            __syncwarp();
            if (lane == 0) {
                FENCE_CLUSTER();
                MBAR_ARRIVE_LOCAL(smb);
#pragma unroll
                for (unsigned pr = 0; pr < 4; pr++)
                    if (pr != rank) MBAR_ARRIVE_REMOTE(smb, pr);
            }
        } else if (wid <= 3) {
            int pt = tid - 32;   // 0..95
            const float* hown = hbuf[nbuf] + rank * 32;
            float r0 = 0.f, r1 = 0.f, r2 = 0.f, r3 = 0.f;
#pragma unroll 8
            for (int k = 0; k < 32; k++) {
                float hk = hown[k];
                const float* w = WCOL + k * 385 + pt;
                r0 += w[0]   * hk; r1 += w[96]  * hk;
                r2 += w[192] * hk; r3 += w[288] * hk;
            }
            float* dst = GHPART + (size_t)(((step + 1) & 1) * 4 + rank) * 384 + pt;
            dst[0] = r0; dst[96] = r1; dst[192] = r2; dst[288] = r3;
            unsigned da = (unsigned)__cvta_generic_to_shared(dst);
#pragma unroll
            for (unsigned pr = 0; pr < 4; pr++)
                if (pr != rank) {
                    unsigned ra = mapa_sh(da, pr);
                    st_remote_f32(ra, r0);
                    st_remote_f32(ra + 96 * 4, r1);
                    st_remote_f32(ra + 192 * 4, r2);
                    st_remote_f32(ra + 288 * 4, r3);
                }
            __syncwarp();
            if (lane == 0) {
                FENCE_CLUSTER();
                MBAR_ARRIVE_LOCAL(gmb);
#pragma unroll
                for (unsigned pr = 0; pr < 4; pr++)
                    if (pr != rank) MBAR_ARRIVE_REMOTE(gmb, pr);
            }
        } else if (wid == 4 || wid == 5) {
            int c = (wid == 4) ? cnd1_s : cnd2_s;
            if (c != 0x7fffffff) {
                const float* gp = g_gi + (size_t)(base + c) * 384 + (int)rank * 32 + lane;
                prefetch_l1(gp); prefetch_l1(gp + 128); prefetch_l1(gp + 256);
            }
        }

        // (k) tid0: wait stats, select, logp, outputs
        if (tid == 0) {
            MBAR_WAIT(smb, step & 1);
            FENCE_CLUSTER();
            float bacc = -INFINITY, bfast = 0.f, gmax = -INFINITY;
            int bnode = 0x7fffffff;
#pragma unroll
            for (int r = 0; r < 4; r++) {
                const float* rw = stats_s[sbuf][r];
#pragma unroll
                for (int c = 0; c < 2; c++) {
                    float a = rw[c ? 3 : 0], f = rw[c ? 4 : 1];
                    int   n = __float_as_int(rw[c ? 5 : 2]);
                    if (a > bacc || (a == bacc && n < bnode)) { bacc = a; bfast = f; bnode = n; }
                }
                if (rw[6] > gmax) gmax = rw[6];
            }
            float denom = 0.f;
#pragma unroll
            for (int r = 0; r < 4; r++) {
                float E = stats_s[sbuf][r][7];
                if (E > 0.f) denom += E * fexpf_(stats_s[sbuf][r][6] - gmax);
            }
            float prob = __fdividef(fexpf_(bfast - gmax), denom);
            float lp = logf(prob + 1e-10f);
            cur_s = bnode;
            if (rank == 0) {
                if (mode == 0) {
                    out_f[b * N_G + step] = (float)(base + curg);
                    out_f[B_G * N_G + b * (N_G - 1) + step] = lp;
                } else if (mode == 1) {
                    out_i[b * N_G + step] = base + curg;
                } else {
                    out_f[b * (N_G - 1) + step] = lp;
                }
            }
        }
        __syncthreads();
    }

    if (rank == 0 && tid == 0) {
        if (mode == 0)      out_f[b * N_G + (N_G - 1)] = (float)(base + cur_s);
        else if (mode == 1) out_i[b * N_G + (N_G - 1)] = base + cur_s;
    }
    CLUSTER_SYNC_();
}

// ---------------- launch ----------------
extern "C" void kernel_launch(void* const* d_in, const int* in_sizes, int n_in,
                              void* d_out, int out_size) {
    const float* emb   = (const float*)d_in[0];
    const int*   start = (const int*)d_in[1];
    const float* Wq1 = (const float*)d_in[3];
    const float* bq1 = (const float*)d_in[4];
    const float* Wq2 = (const float*)d_in[5];
    const float* bq2 = (const float*)d_in[6];
    const float* Wk1 = (const float*)d_in[7];
    const float* bk1 = (const float*)d_in[8];
    const float* Wk2 = (const float*)d_in[9];
    const float* bk2 = (const float*)d_in[10];
    const float* W_ih = (const float*)d_in[11];
    const float* W_hh = (const float*)d_in[12];
    const float* b_ih = (const float*)d_in[13];
    const float* b_hh = (const float*)d_in[14];
    const float* v    = (const float*)d_in[15];
    const float* Wh   = (const float*)d_in[16];
    const float* bh   = (const float*)d_in[17];
    (void)in_sizes; (void)n_in;

    void *p_tmp, *p_keys;
    cudaGetSymbolAddress(&p_tmp, g_tmp);
    cudaGetSymbolAddress(&p_keys, g_keys);
    float* tmp  = (float*)p_tmp;
    float* keys = (float*)p_keys;

    gemm_fused<<<1024, 256>>>(emb, Wk1, bk1, W_ih, b_ih);
    gemm_tn<<<dim3(T_G / 64, D_G / 64), 256>>>(tmp, Wk2, bk2, keys, D_G, 0);
    l2norm_rows<<<T_G / 8, 256>>>(keys, T_G);

    int mode = 0;
    if (out_size == B_G * N_G + B_G * (N_G - 1)) mode = 0;
    else if (out_size == B_G * N_G) mode = 1;
    else if (out_size == B_G * (N_G - 1)) mode = 2;

    static int smem_set = -1;
    size_t dyn = DYN_FLOATS * sizeof(float);
    if (smem_set < 0) {
        cudaFuncSetAttribute(decode_kernel,
                             cudaFuncAttributeMaxDynamicSharedMemorySize, (int)dyn);
        smem_set = 1;
    }
    decode_kernel<<<B_G * 4, 256, dyn>>>(emb, start, W_hh, b_hh,
                                         Wq1, bq1, Wq2, bq2, Wh, bh, v,
                                         (float*)d_out, (int*)d_out, mode);
}

// round 17
// speedup vs baseline: 2.4162x; 1.0721x over previous
#include <cuda_runtime.h>
#include <math.h>

#define B_G 32
#define N_G 256
#define D_G 128
#define T_G 8192

// ---------------- device scratch (no allocation) ----------------
__device__ float g_tmp[T_G * D_G];
__device__ float g_keys[T_G * D_G];
__device__ float g_gi[T_G * 3 * D_G];

// ---------------- fast math ----------------
__device__ __forceinline__ float fexp2(float x) {
    float y; asm("ex2.approx.f32 %0, %1;" : "=f"(y) : "f"(x)); return y;
}
__device__ __forceinline__ float fexpf_(float x) { return fexp2(x * 1.4426950408889634f); }
__device__ __forceinline__ float ftanh(float x) {
    float e = fexp2(x * 2.8853900817779268f);
    return 1.0f - __fdividef(2.0f, e + 1.0f);
}

// ---------------- cluster/mbarrier helpers ----------------
__device__ __forceinline__ unsigned mapa_sh(unsigned a, unsigned r) {
    unsigned o; asm("mapa.shared::cluster.u32 %0, %1, %2;" : "=r"(o) : "r"(a), "r"(r));
    return o;
}
__device__ __forceinline__ unsigned ctarank() {
    unsigned r; asm("mov.u32 %0, %%cluster_ctarank;" : "=r"(r)); return r;
}
__device__ __forceinline__ void st_remote_f32(unsigned addr, float v) {
    asm volatile("st.shared::cluster.f32 [%0], %1;" :: "r"(addr), "f"(v) : "memory");
}
__device__ __forceinline__ void prefetch_l1(const float* p) {
    asm volatile("prefetch.global.L1 [%0];" :: "l"(p));
}
#define MBAR_INIT(a, c) \
    asm volatile("mbarrier.init.shared.b64 [%0], %1;" :: "r"(a), "r"(c) : "memory")
#define MBAR_ARRIVE_LOCAL(a) \
    asm volatile("mbarrier.arrive.shared.b64 _, [%0];" :: "r"(a) : "memory")
#define MBAR_ARRIVE_REMOTE(a, rk) \
    asm volatile("{\n\t.reg .b32 ra;\n\tmapa.shared::cluster.u32 ra, %0, %1;\n\t" \
                 "mbarrier.arrive.shared::cluster.b64 _, [ra];\n\t}" \
                 :: "r"(a), "r"(rk) : "memory")
#define MBAR_WAIT(mbar, par) do {                                             \
    unsigned _m = (mbar), _p = (par), _d;                                     \
    asm volatile("{\n\t.reg .pred p;\n\t"                                     \
        "mbarrier.try_wait.parity.acquire.cta.shared::cta.b64 p, [%1], %2;\n\t" \
        "selp.b32 %0, 1, 0, p;\n\t}"                                          \
        : "=r"(_d) : "r"(_m), "r"(_p) : "memory");                            \
    if (!_d) {                                                                \
        asm volatile("{\n\t.reg .pred P1;\n\tWL%=:\n\t"                       \
            "mbarrier.try_wait.parity.acquire.cta.shared::cta.b64 P1, [%0], %1, 0x989680;\n\t" \
            "@P1 bra WD%=;\n\tbra WL%=;\n\tWD%=:\n\t}"                        \
            :: "r"(_m), "r"(_p) : "memory");                                  \
    }                                                                         \
} while (0)
#define FENCE_CLUSTER() asm volatile("fence.acq_rel.cluster;" ::: "memory")
#define CLUSTER_SYNC_() do {                                        \
    asm volatile("barrier.cluster.arrive.aligned;" ::: "memory");   \
    asm volatile("barrier.cluster.wait.aligned;"   ::: "memory");   \
} while (0)

// ---------------- precompute GEMMs (R10-proven) ----------------
__device__ __forceinline__ void gemm_tile(
    const float* __restrict__ A, const float* __restrict__ W,
    const float* __restrict__ bias, float* __restrict__ C,
    int N, int relu, int m0, int n0, int tid)
{
    __shared__ float As[64 * 129];
    __shared__ float Ws[64 * 129];

    for (int i = tid; i < 64 * 32; i += 256) {
        int r = i >> 5, kq = i & 31;
        float4 a = *((const float4*)(A + (size_t)(m0 + r) * 128) + kq);
        float* p = As + r * 129 + kq * 4;
        p[0] = a.x; p[1] = a.y; p[2] = a.z; p[3] = a.w;
        float4 w = *((const float4*)(W + (size_t)(n0 + r) * 128) + kq);
        float* pw = Ws + r * 129 + kq * 4;
        pw[0] = w.x; pw[1] = w.y; pw[2] = w.z; pw[3] = w.w;
    }
    __syncthreads();

    const int tx = tid & 15, ty = tid >> 4;
    float acc[4][4] = {};
    const float* ap = As + ty * 4 * 129;
    const float* wp = Ws + tx * 4 * 129;
#pragma unroll 4
    for (int k = 0; k < 128; k++) {
        float a0 = ap[k], a1 = ap[129 + k], a2 = ap[258 + k], a3 = ap[387 + k];
        float w0 = wp[k], w1 = wp[129 + k], w2 = wp[258 + k], w3 = wp[387 + k];
        acc[0][0] += a0 * w0; acc[0][1] += a0 * w1; acc[0][2] += a0 * w2; acc[0][3] += a0 * w3;
        acc[1][0] += a1 * w0; acc[1][1] += a1 * w1; acc[1][2] += a1 * w2; acc[1][3] += a1 * w3;
        acc[2][0] += a2 * w0; acc[2][1] += a2 * w1; acc[2][2] += a2 * w2; acc[2][3] += a2 * w3;
        acc[3][0] += a3 * w0; acc[3][1] += a3 * w1; acc[3][2] += a3 * w2; acc[3][3] += a3 * w3;
    }

    float4 b4;
    b4.x = bias[n0 + tx * 4 + 0]; b4.y = bias[n0 + tx * 4 + 1];
    b4.z = bias[n0 + tx * 4 + 2]; b4.w = bias[n0 + tx * 4 + 3];
#pragma unroll
    for (int i = 0; i < 4; i++) {
        float4 o;
        o.x = acc[i][0] + b4.x; o.y = acc[i][1] + b4.y;
        o.z = acc[i][2] + b4.z; o.w = acc[i][3] + b4.w;
        if (relu) {
            o.x = fmaxf(o.x, 0.f); o.y = fmaxf(o.y, 0.f);
            o.z = fmaxf(o.z, 0.f); o.w = fmaxf(o.w, 0.f);
        }
        *(float4*)(C + (size_t)(m0 + ty * 4 + i) * N + n0 + tx * 4) = o;
    }
}

__global__ __launch_bounds__(256) void gemm_fused(
    const float* __restrict__ emb,
    const float* __restrict__ Wk1, const float* __restrict__ bk1,
    const float* __restrict__ Wih, const float* __restrict__ bih)
{
    int bx = blockIdx.x;
    if (bx < 256)
        gemm_tile(emb, Wk1, bk1, g_tmp, 128, 1, (bx >> 1) * 64, (bx & 1) * 64, threadIdx.x);
    else {
        int j = bx - 256;
        gemm_tile(emb, Wih, bih, g_gi, 384, 0, (j / 6) * 64, (j % 6) * 64, threadIdx.x);
    }
}

__global__ __launch_bounds__(256) void gemm_tn(
    const float* __restrict__ A, const float* __restrict__ W,
    const float* __restrict__ bias, float* __restrict__ C, int N, int relu)
{
    gemm_tile(A, W, bias, C, N, relu, blockIdx.x * 64, blockIdx.y * 64, threadIdx.x);
}

__global__ void l2norm_rows(float* __restrict__ X, int rows)
{
    int wid = threadIdx.x >> 5, lane = threadIdx.x & 31;
    int row = blockIdx.x * 8 + wid;
    if (row >= rows) return;
    float4* p = (float4*)(X + (size_t)row * 128) + lane;
    float4 x = *p;
    float ss = x.x * x.x + x.y * x.y + x.z * x.z + x.w * x.w;
#pragma unroll
    for (int o = 16; o; o >>= 1) ss += __shfl_xor_sync(0xffffffffu, ss, o);
    float rn = 1.0f / fmaxf(sqrtf(ss), 1e-12f);
    x.x *= rn; x.y *= rn; x.z *= rn; x.w *= rn;
    *p = x;
}

// ---------------- clustered decoder: redundant GRU + fused exchange phase --
#define WCOL_OFF 0
#define KEY_OFF  12320
#define GHP_OFF  20512
#define DYN_FLOATS 23584

__global__ __launch_bounds__(256, 1) __cluster_dims__(4, 1, 1)
void decode_kernel(
    const float* __restrict__ emb, const int* __restrict__ start_nodes,
    const float* __restrict__ W_hh, const float* __restrict__ b_hh,
    const float* __restrict__ Wq1, const float* __restrict__ bq1,
    const float* __restrict__ Wq2, const float* __restrict__ bq2,
    const float* __restrict__ Wh,  const float* __restrict__ bh,
    const float* __restrict__ v,
    float* __restrict__ out_f, int* __restrict__ out_i, int mode)
{
    extern __shared__ float dyn[];
    float* WCOL   = dyn + WCOL_OFF;   // [k*385 + j], k<32, j<384
    float* KEYS   = dyn + KEY_OFF;    // [n*128 + d], n<64
    float* GHPART = dyn + GHP_OFF;    // [(pb*4 + r)*384 + j]

    __shared__ __align__(16) float hbuf[2][128];
    __shared__ __align__(16) float q_s[128], hq_s[128], gctx_s[128];
    __shared__ float stats_s[2][4][8];
    __shared__ float bhh_s[384], bq1_s[128], bq2_s[128];
    __shared__ float wm1[8], wm2[8], we_s[8], red_s[8];
    __shared__ int   wn1[8], wn2[8];
    __shared__ int   list_s[64], pos_s[64];
    __shared__ int   cnt_s, cur_s;
    __shared__ __align__(8) unsigned long long stat_mbar, gh_mbar;

    const int tid  = threadIdx.x;
    const int lane = tid & 31, wid = tid >> 5;
    const unsigned rank = ctarank();
    const int b    = blockIdx.x >> 2;
    const int base = b * N_G;

    // register-resident Wq1/Wq2: 2 threads per output, 64 floats each
    const int ro = tid >> 1, rkh = tid & 1;
    float4 w1r[16], w2r[16];
    {
        const float4* p1 = (const float4*)(Wq1 + (size_t)ro * 128 + rkh * 64);
        const float4* p2 = (const float4*)(Wq2 + (size_t)ro * 128 + rkh * 64);
#pragma unroll
        for (int j = 0; j < 16; j++) { w1r[j] = p1[j]; w2r[j] = p2[j]; }
    }

    // ---- staging ----
    for (int idx = tid; idx < 384 * 32; idx += 256) {   // W_hh column slice
        int j = idx >> 5, k = idx & 31;
        WCOL[k * 385 + j] = W_hh[(size_t)j * 128 + rank * 32 + k];
    }
    for (int idx = tid; idx < 64 * 32; idx += 256) {    // own 64 keys
        int n = idx >> 5, kq = idx & 31;
        ((float4*)(KEYS + n * 128))[kq] =
            *((const float4*)(g_keys + (size_t)(base + (int)rank * 64 + n) * 128) + kq);
    }
    for (int i = tid; i < 384; i += 256) bhh_s[i] = b_hh[i];
    if (tid < 128) { bq1_s[tid] = bq1[tid]; bq2_s[tid] = bq2[tid]; }
    if (tid < 64) { list_s[tid] = tid; pos_s[tid] = tid; }
    if (tid == 0) {
        cnt_s = 64; cur_s = start_nodes[b] - base;
        MBAR_INIT((unsigned)__cvta_generic_to_shared(&stat_mbar), 12);
        MBAR_INIT((unsigned)__cvta_generic_to_shared(&gh_mbar), 12);
    }
    if (tid < 128) {
        float acc = 0.f;
        const float* ep = emb + (size_t)base * 128 + tid;
#pragma unroll 8
        for (int n = 0; n < 256; n++) acc += ep[n * 128];
        gctx_s[tid] = acc * (1.0f / 256.0f);
    }
    __syncthreads();
    {
        float4 g4 = *((const float4*)gctx_s + lane);
#pragma unroll
        for (int i = 0; i < 16; i++) {
            int r = wid * 16 + i;
            float4 w4 = *((const float4*)(Wh + (size_t)r * 128) + lane);
            float s = w4.x * g4.x + w4.y * g4.y + w4.z * g4.z + w4.w * g4.w;
#pragma unroll
            for (int o = 16; o; o >>= 1) s += __shfl_xor_sync(0xffffffffu, s, o);
            if (lane == 0) hbuf[0][r] = s + bh[r];
        }
    }
    float4 v4 = *((const float4*)v + lane);
    __syncthreads();
    CLUSTER_SYNC_();

    const unsigned smb = (unsigned)__cvta_generic_to_shared(&stat_mbar);
    const unsigned gmb = (unsigned)__cvta_generic_to_shared(&gh_mbar);

    // ---- prologue: gh(0) partials (warps 3-5 pattern uses tid-96 here) ----
    if (wid >= 1 && wid <= 3) {
        int pt = tid - 32;   // 0..95
        const float* hown = hbuf[0] + rank * 32;
        float r0 = 0.f, r1 = 0.f, r2 = 0.f, r3 = 0.f;
#pragma unroll 8
        for (int k = 0; k < 32; k++) {
            float hk = hown[k];
            const float* w = WCOL + k * 385 + pt;
            r0 += w[0]   * hk; r1 += w[96]  * hk;
            r2 += w[192] * hk; r3 += w[288] * hk;
        }
        float* dst = GHPART + (0 * 4 + rank) * 384 + pt;
        dst[0] = r0; dst[96] = r1; dst[192] = r2; dst[288] = r3;
        unsigned da = (unsigned)__cvta_generic_to_shared(dst);
#pragma unroll
        for (unsigned pr = 0; pr < 4; pr++)
            if (pr != rank) {
                unsigned ra = mapa_sh(da, pr);
                st_remote_f32(ra, r0);
                st_remote_f32(ra + 96 * 4, r1);
                st_remote_f32(ra + 192 * 4, r2);
                st_remote_f32(ra + 288 * 4, r3);
            }
        __syncwarp();
        if (lane == 0) {
            FENCE_CLUSTER();
            MBAR_ARRIVE_LOCAL(gmb);
#pragma unroll
            for (unsigned pr = 0; pr < 4; pr++)
                if (pr != rank) MBAR_ARRIVE_REMOTE(gmb, pr);
        }
    }

    for (int step = 0; step < N_G - 1; step++) {
        const int buf = step & 1, nbuf = buf ^ 1, sbuf = step & 1;
        const int curg = cur_s;

        // (d) GRU full + redundant (threads 0-127); tid 128 maintains list
        if (tid < 128) {
            MBAR_WAIT(gmb, step & 1);
            FENCE_CLUSTER();
            const float* P = GHPART + (size_t)(step & 1) * 4 * 384;
            float gh_r = ((P[tid]        + P[384 + tid])
                        + (P[768 + tid]  + P[1152 + tid])) + bhh_s[tid];
            float gh_z = ((P[128 + tid]  + P[512 + tid])
                        + (P[896 + tid]  + P[1280 + tid])) + bhh_s[128 + tid];
            float gh_n = ((P[256 + tid]  + P[640 + tid])
                        + (P[1024 + tid] + P[1408 + tid])) + bhh_s[256 + tid];
            const float* gip = g_gi + (size_t)(base + curg) * 384 + tid;
            float gi_r = __ldg(gip);
            float gi_z = __ldg(gip + 128);
            float gi_n = __ldg(gip + 256);
            float gr_ = 1.f / (1.f + expf(-(gi_r + gh_r)));
            float gz  = 1.f / (1.f + expf(-(gi_z + gh_z)));
            float gn  = tanhf(gi_n + gr_ * gh_n);
            hbuf[nbuf][tid] = (1.f - gz) * gn + gz * hbuf[buf][tid];
        } else if (tid == 128) {
            if ((curg >> 6) == (int)rank) {
                int nl = curg & 63;
                int p = pos_s[nl], last = cnt_s - 1;
                int tail = list_s[last];
                list_s[p] = tail; pos_s[tail] = p;
                cnt_s = last;
            }
        }
        __syncthreads();

        // (e) stage1: Wq1 in registers
        {
            const float4* h4p = (const float4*)(hbuf[nbuf] + rkh * 64);
            float p0 = 0.f, p1 = 0.f, p2 = 0.f, p3 = 0.f;
#pragma unroll
            for (int j = 0; j < 16; j += 4) {
                float4 h0 = h4p[j], h1 = h4p[j + 1], h2 = h4p[j + 2], h3 = h4p[j + 3];
                p0 += w1r[j].x * h0.x + w1r[j].y * h0.y + w1r[j].z * h0.z + w1r[j].w * h0.w;
                p1 += w1r[j+1].x * h1.x + w1r[j+1].y * h1.y + w1r[j+1].z * h1.z + w1r[j+1].w * h1.w;
                p2 += w1r[j+2].x * h2.x + w1r[j+2].y * h2.y + w1r[j+2].z * h2.z + w1r[j+2].w * h2.w;
                p3 += w1r[j+3].x * h3.x + w1r[j+3].y * h3.y + w1r[j+3].z * h3.z + w1r[j+3].w * h3.w;
            }
            float p = (p0 + p1) + (p2 + p3);
            p += __shfl_xor_sync(0xffffffffu, p, 1);
            if (rkh == 0) hq_s[ro] = fmaxf(p + bq1_s[ro], 0.f);
        }
        __syncthreads();

        // (f) stage2 + q sum-of-squares partials
        {
            const float4* h4p = (const float4*)(hq_s + rkh * 64);
            float p0 = 0.f, p1 = 0.f, p2 = 0.f, p3 = 0.f;
#pragma unroll
            for (int j = 0; j < 16; j += 4) {
                float4 h0 = h4p[j], h1 = h4p[j + 1], h2 = h4p[j + 2], h3 = h4p[j + 3];
                p0 += w2r[j].x * h0.x + w2r[j].y * h0.y + w2r[j].z * h0.z + w2r[j].w * h0.w;
                p1 += w2r[j+1].x * h1.x + w2r[j+1].y * h1.y + w2r[j+1].z * h1.z + w2r[j+1].w * h1.w;
                p2 += w2r[j+2].x * h2.x + w2r[j+2].y * h2.y + w2r[j+2].z * h2.z + w2r[j+2].w * h2.w;
                p3 += w2r[j+3].x * h3.x + w2r[j+3].y * h3.y + w2r[j+3].z * h3.z + w2r[j+3].w * h3.w;
            }
            float p = (p0 + p1) + (p2 + p3);
            p += __shfl_xor_sync(0xffffffffu, p, 1);
            float qv = 0.f;
            if (rkh == 0) { qv = p + bq2_s[ro]; q_s[ro] = qv; }
            float q2 = qv * qv;
#pragma unroll
            for (int o = 16; o; o >>= 1) q2 += __shfl_xor_sync(0xffffffffu, q2, o);
            if (lane == 0) red_s[wid] = q2;
        }
        __syncthreads();

        const int cnt = cnt_s;
        const float rn = rsqrtf(fmaxf(red_s[0] + red_s[1] + red_s[2] + red_s[3]
                                    + red_s[4] + red_s[5] + red_s[6] + red_s[7], 1e-24f));
        float4 q4 = *((const float4*)q_s + lane);
        q4.x *= rn; q4.y *= rn; q4.z *= rn; q4.w *= rn;

        // (g) scoring: all 8 warps, smem keys, 2-node ILP
        {
            float m1 = -INFINITY, m2 = -INFINITY, em = -INFINITY, esum = 0.f;
            int n1 = 0x7fffffff, n2 = 0x7fffffff;
            for (int p = wid; p < cnt; p += 16) {
                int nlA = list_s[p];
                int pB = p + 8;
                bool hasB = pB < cnt;
                int nlB = hasB ? list_s[pB] : nlA;
                float4 kA = *((const float4*)(KEYS + nlA * 128) + lane);
                float4 kB = *((const float4*)(KEYS + nlB * 128) + lane);
                float sA = v4.x * ftanh(kA.x + q4.x) + v4.y * ftanh(kA.y + q4.y)
                         + v4.z * ftanh(kA.z + q4.z) + v4.w * ftanh(kA.w + q4.w);
                float sB = v4.x * ftanh(kB.x + q4.x) + v4.y * ftanh(kB.y + q4.y)
                         + v4.z * ftanh(kB.z + q4.z) + v4.w * ftanh(kB.w + q4.w);
#pragma unroll
                for (int o = 16; o; o >>= 1) {
                    sA += __shfl_xor_sync(0xffffffffu, sA, o);
                    sB += __shfl_xor_sync(0xffffffffu, sB, o);
                }
                if (lane == 0) {
                    int ngA = (int)rank * 64 + nlA;
                    if (sA > m1 || (sA == m1 && ngA < n1)) { m2 = m1; n2 = n1; m1 = sA; n1 = ngA; }
                    else if (sA > m2 || (sA == m2 && ngA < n2)) { m2 = sA; n2 = ngA; }
                    float sB2 = hasB ? sB : -INFINITY;
                    if (hasB) {
                        int ngB = (int)rank * 64 + nlB;
                        if (sB > m1 || (sB == m1 && ngB < n1)) { m2 = m1; n2 = n1; m1 = sB; n1 = ngB; }
                        else if (sB > m2 || (sB == m2 && ngB < n2)) { m2 = sB; n2 = ngB; }
                    }
                    float mn = fmaxf(em, fmaxf(sA, sB2));
                    esum = esum * fexpf_(em - mn) + fexpf_(sA - mn) + fexpf_(sB2 - mn);
                    em = mn;
                }
            }
            if (lane == 0) {
                wm1[wid] = m1; wn1[wid] = n1; wm2[wid] = m2; wn2[wid] = n2;
                we_s[wid] = esum;
            }
        }
        __syncthreads();

        // (h+j fused, warp-specialized; NO sync inside)
        float* row = stats_s[sbuf][rank];
        if (wid < 2 || wid >= 6) {
            // redundant top2 merge (warps 0,1,6,7)
            float bm1 = -INFINITY, bm2 = -INFINITY;
            int bn1 = 0x7fffffff, bn2 = 0x7fffffff;
#pragma unroll
            for (int w = 0; w < 8; w++) {
#pragma unroll
                for (int c = 0; c < 2; c++) {
                    float s = c ? wm2[w] : wm1[w];
                    int   n = c ? wn2[w] : wn1[w];
                    if (s > bm1 || (s == bm1 && n < bn1)) { bm2 = bm1; bn2 = bn1; bm1 = s; bn1 = n; }
                    else if (s > bm2 || (s == bm2 && n < bn2)) { bm2 = s; bn2 = n; }
                }
            }
            if (wid < 2) {
                // rescore own candidate accurately, write + push + arrive
                int mycnd = wid ? bn2 : bn1;
                float acc = -INFINITY;
                if (mycnd != 0x7fffffff) {
                    int nl = mycnd & 63;
                    float4 k4 = *((const float4*)(KEYS + nl * 128) + lane);
                    float s = v4.x * tanhf(k4.x + q4.x) + v4.y * tanhf(k4.y + q4.y)
                            + v4.z * tanhf(k4.z + q4.z) + v4.w * tanhf(k4.w + q4.w);
#pragma unroll
                    for (int o = 16; o; o >>= 1) s += __shfl_xor_sync(0xffffffffu, s, o);
                    acc = s;
                }
                if (wid == 0) {
                    if (lane == 0) {
                        row[0] = acc;
                        row[1] = bm1; row[2] = __int_as_float(bn1);
                        row[4] = bm2; row[5] = __int_as_float(bn2);
                    }
                    __syncwarp();
                    if (lane < 6) {
                        int j = (lane < 3) ? lane : lane + 1;   // fields 0,1,2,4,5 (+1 dup)
                        if (lane == 5) j = 5;
                        float val = row[j];
                        unsigned ra = (unsigned)__cvta_generic_to_shared(&row[j]);
#pragma unroll
                        for (unsigned pr = 0; pr < 4; pr++)
                            if (pr != rank) st_remote_f32(mapa_sh(ra, pr), val);
                    }
                    __syncwarp();
                    if (lane == 0) {
                        FENCE_CLUSTER();
                        MBAR_ARRIVE_LOCAL(smb);
#pragma unroll
                        for (unsigned pr = 0; pr < 4; pr++)
                            if (pr != rank) MBAR_ARRIVE_REMOTE(smb, pr);
                    }
                } else {
                    if (lane == 0) {
                        row[3] = acc;
                        unsigned ra = (unsigned)__cvta_generic_to_shared(&row[3]);
#pragma unroll
                        for (unsigned pr = 0; pr < 4; pr++)
                            if (pr != rank) st_remote_f32(mapa_sh(ra, pr), acc);
                        FENCE_CLUSTER();
                        MBAR_ARRIVE_LOCAL(smb);
#pragma unroll
                        for (unsigned pr = 0; pr < 4; pr++)
                            if (pr != rank) MBAR_ARRIVE_REMOTE(smb, pr);
                    }
                }
            } else {
                // warps 6,7: prefetch full gi rows of cnd1/cnd2
                int c = (wid == 6) ? bn1 : bn2;
                if (c != 0x7fffffff && lane < 12)
                    prefetch_l1(g_gi + (size_t)(base + c) * 384 + lane * 32);
            }
        } else if (wid == 2) {
            // (M,E) merge + push + arrive
            float mw = (lane < 8) ? wm1[lane] : -INFINITY;
            float ew = (lane < 8) ? we_s[lane] : 0.f;
            float M = mw;
#pragma unroll
            for (int o = 16; o; o >>= 1) M = fmaxf(M, __shfl_xor_sync(0xffffffffu, M, o));
            float term = (ew > 0.f) ? ew * fexpf_(mw - M) : 0.f;  // NaN guard
#pragma unroll
            for (int o = 16; o; o >>= 1) term += __shfl_xor_sync(0xffffffffu, term, o);
            if (lane == 0) {
                row[6] = M; row[7] = term;
                unsigned ra6 = (unsigned)__cvta_generic_to_shared(&row[6]);
                unsigned ra7 = (unsigned)__cvta_generic_to_shared(&row[7]);
#pragma unroll
                for (unsigned pr = 0; pr < 4; pr++)
                    if (pr != rank) {
                        st_remote_f32(mapa_sh(ra6, pr), M);
                        st_remote_f32(mapa_sh(ra7, pr), term);
                    }
                FENCE_CLUSTER();
                MBAR_ARRIVE_LOCAL(smb);
#pragma unroll
                for (unsigned pr = 0; pr < 4; pr++)
                    if (pr != rank) MBAR_ARRIVE_REMOTE(smb, pr);
            }
        } else {
            // warps 3-5: gh(t+1) partials + push + arrive (shadowed)
            int pt = tid - 96;   // 0..95
            const float* hown = hbuf[nbuf] + rank * 32;
            float r0 = 0.f, r1 = 0.f, r2 = 0.f, r3 = 0.f;
#pragma unroll 8
            for (int k = 0; k < 32; k++) {
                float hk = hown[k];
                const float* w = WCOL + k * 385 + pt;
                r0 += w[0]   * hk; r1 += w[96]  * hk;
                r2 += w[192] * hk; r3 += w[288] * hk;
            }
            float* dst = GHPART + (size_t)(((step + 1) & 1) * 4 + rank) * 384 + pt;
            dst[0] = r0; dst[96] = r1; dst[192] = r2; dst[288] = r3;
            unsigned da = (unsigned)__cvta_generic_to_shared(dst);
#pragma unroll
            for (unsigned pr = 0; pr < 4; pr++)
                if (pr != rank) {
                    unsigned ra = mapa_sh(da, pr);
                    st_remote_f32(ra, r0);
                    st_remote_f32(ra + 96 * 4, r1);
                    st_remote_f32(ra + 192 * 4, r2);
                    st_remote_f32(ra + 288 * 4, r3);
                }
            __syncwarp();
            if (lane == 0) {
                FENCE_CLUSTER();
                MBAR_ARRIVE_LOCAL(gmb);
#pragma unroll
                for (unsigned pr = 0; pr < 4; pr++)
                    if (pr != rank) MBAR_ARRIVE_REMOTE(gmb, pr);
            }
        }

        // (k) tid0: wait stats, select, logp, outputs
        if (tid == 0) {
            MBAR_WAIT(smb, step & 1);
            FENCE_CLUSTER();
            float bacc = -INFINITY, bfast = 0.f, gmax = -INFINITY;
            int bnode = 0x7fffffff;
#pragma unroll
            for (int r = 0; r < 4; r++) {
                const float* rw = stats_s[sbuf][r];
#pragma unroll
                for (int c = 0; c < 2; c++) {
                    float a = rw[c ? 3 : 0], f = rw[c ? 4 : 1];
                    int   n = __float_as_int(rw[c ? 5 : 2]);
                    if (a > bacc || (a == bacc && n < bnode)) { bacc = a; bfast = f; bnode = n; }
                }
                if (rw[6] > gmax) gmax = rw[6];
            }
            float denom = 0.f;
#pragma unroll
            for (int r = 0; r < 4; r++) {
                float E = stats_s[sbuf][r][7];
                if (E > 0.f) denom += E * fexpf_(stats_s[sbuf][r][6] - gmax);
            }
            float prob = __fdividef(fexpf_(bfast - gmax), denom);
            float lp = __logf(prob + 1e-10f);
            cur_s = bnode;
            if (rank == 0) {
                if (mode == 0) {
                    out_f[b * N_G + step] = (float)(base + curg);
                    out_f[B_G * N_G + b * (N_G - 1) + step] = lp;
                } else if (mode == 1) {
                    out_i[b * N_G + step] = base + curg;
                } else {
                    out_f[b * (N_G - 1) + step] = lp;
                }
            }
        }
        __syncthreads();
    }

    if (rank == 0 && tid == 0) {
        if (mode == 0)      out_f[b * N_G + (N_G - 1)] = (float)(base + cur_s);
        else if (mode == 1) out_i[b * N_G + (N_G - 1)] = base + cur_s;
    }
    CLUSTER_SYNC_();
}

// ---------------- launch ----------------
extern "C" void kernel_launch(void* const* d_in, const int* in_sizes, int n_in,
                              void* d_out, int out_size) {
    const float* emb   = (const float*)d_in[0];
    const int*   start = (const int*)d_in[1];
    const float* Wq1 = (const float*)d_in[3];
    const float* bq1 = (const float*)d_in[4];
    const float* Wq2 = (const float*)d_in[5];
    const float* bq2 = (const float*)d_in[6];
    const float* Wk1 = (const float*)d_in[7];
    const float* bk1 = (const float*)d_in[8];
    const float* Wk2 = (const float*)d_in[9];
    const float* bk2 = (const float*)d_in[10];
    const float* W_ih = (const float*)d_in[11];
    const float* W_hh = (const float*)d_in[12];
    const float* b_ih = (const float*)d_in[13];
    const float* b_hh = (const float*)d_in[14];
    const float* v    = (const float*)d_in[15];
    const float* Wh   = (const float*)d_in[16];
    const float* bh   = (const float*)d_in[17];
    (void)in_sizes; (void)n_in;

    void *p_tmp, *p_keys;
    cudaGetSymbolAddress(&p_tmp, g_tmp);
    cudaGetSymbolAddress(&p_keys, g_keys);
    float* tmp  = (float*)p_tmp;
    float* keys = (float*)p_keys;

    gemm_fused<<<1024, 256>>>(emb, Wk1, bk1, W_ih, b_ih);
    gemm_tn<<<dim3(T_G / 64, D_G / 64), 256>>>(tmp, Wk2, bk2, keys, D_G, 0);
    l2norm_rows<<<T_G / 8, 256>>>(keys, T_G);

    int mode = 0;
    if (out_size == B_G * N_G + B_G * (N_G - 1)) mode = 0;
    else if (out_size == B_G * N_G) mode = 1;
    else if (out_size == B_G * (N_G - 1)) mode = 2;

    static int smem_set = -1;
    size_t dyn = DYN_FLOATS * sizeof(float);
    if (smem_set < 0) {
        cudaFuncSetAttribute(decode_kernel,
                             cudaFuncAttributeMaxDynamicSharedMemorySize, (int)dyn);
        smem_set = 1;
    }
    decode_kernel<<<B_G * 4, 256, dyn>>>(emb, start, W_hh, b_hh,
                                         Wq1, bq1, Wq2, bq2, Wh, bh, v,
                                         (float*)d_out, (int*)d_out, mode);
}